// round 1
// baseline (speedup 1.0000x reference)
#include <cuda_runtime.h>
#include <math.h>

#define VOCAB 50000
#define EMB   300
#define SEQ   80
#define HID   128
#define BATCH 4096

// Scratch: projected embedding table P = emb @ Wxh  (25.6 MB, L2-resident at use time)
__device__ float g_P[VOCAB * HID];

// ---------------------------------------------------------------------------
// Kernel A: P[v][j] = sum_e emb[v][e] * Wxh[e][j]
// Tiles: TM=64 rows x TN=128 cols, TK=4. 256 threads, 4x8 per-thread tile.
// ---------------------------------------------------------------------------
#define TM 64
#define TK 4

__global__ __launch_bounds__(256) void proj_kernel(const float* __restrict__ emb,
                                                   const float* __restrict__ Wxh) {
    __shared__ float As[TK][TM];    // [k][row]
    __shared__ float Bs[TK][HID];   // [k][col]

    const int v0   = blockIdx.x * TM;
    const int tid  = threadIdx.x;
    const int trow = tid >> 4;      // 0..15 -> rows trow*4 .. +3
    const int tcol = tid & 15;      // 0..15 -> cols tcol*8 .. +7

    float acc[4][8];
#pragma unroll
    for (int i = 0; i < 4; i++)
#pragma unroll
        for (int j = 0; j < 8; j++) acc[i][j] = 0.f;

    for (int e0 = 0; e0 < EMB; e0 += TK) {   // 300 % 4 == 0
        // Load As: 64x4 = 256 floats, one per thread
        {
            const int i = tid >> 2;
            const int k = tid & 3;
            const int v = v0 + i;
            As[k][i] = (v < VOCAB) ? emb[(long)v * EMB + e0 + k] : 0.f;
        }
        // Load Bs: 4x128 = 512 floats, two per thread
        {
            int idx = tid;
            Bs[idx >> 7][idx & 127] = Wxh[(e0 + (idx >> 7)) * HID + (idx & 127)];
            idx += 256;
            Bs[idx >> 7][idx & 127] = Wxh[(e0 + (idx >> 7)) * HID + (idx & 127)];
        }
        __syncthreads();

#pragma unroll
        for (int k = 0; k < TK; k++) {
            float a[4], b[8];
#pragma unroll
            for (int i = 0; i < 4; i++) a[i] = As[k][trow * 4 + i];
#pragma unroll
            for (int j = 0; j < 8; j++) b[j] = Bs[k][tcol * 8 + j];
#pragma unroll
            for (int i = 0; i < 4; i++)
#pragma unroll
                for (int j = 0; j < 8; j++) acc[i][j] += a[i] * b[j];
        }
        __syncthreads();
    }

#pragma unroll
    for (int i = 0; i < 4; i++) {
        const int v = v0 + trow * 4 + i;
        if (v < VOCAB) {
#pragma unroll
            for (int j = 0; j < 8; j++)
                g_P[(long)v * HID + tcol * 8 + j] = acc[i][j];
        }
    }
}

// ---------------------------------------------------------------------------
// Kernel B: per-block local recurrence over 8 batch rows, all 80 timesteps.
//   h = tanh(P[tok] + bh + h @ Whh), then out = sigmoid(h . Wd + bd)
// 128 threads: rowgroup = tid/64 (4 rows each), jt = tid%64 -> cols jt, jt+64.
// Whh lives in shared (64 KB); next timestep's P rows prefetched into regs.
// ---------------------------------------------------------------------------
__global__ __launch_bounds__(128) void rnn_kernel(const int* __restrict__ x,
                                                  const float* __restrict__ Whh,
                                                  const float* __restrict__ bh,
                                                  const float* __restrict__ Wd,
                                                  const float* __restrict__ bd,
                                                  float* __restrict__ out) {
    extern __shared__ float sh[];
    float* Whh_sh = sh;                       // HID*HID
    float* h_sh   = Whh_sh + HID * HID;       // 8*HID
    int*   tok_sh = (int*)(h_sh + 8 * HID);   // 8*SEQ

    const int tid = threadIdx.x;
    const int rg  = tid >> 6;                 // 0..1
    const int jt  = tid & 63;
    const int j0  = jt, j1 = jt + 64;
    const int b0  = blockIdx.x * 8;

    for (int i = tid; i < HID * HID; i += 128) Whh_sh[i] = Whh[i];
    for (int i = tid; i < 8 * SEQ; i += 128) {
        const int r = i / SEQ, t = i % SEQ;
        tok_sh[r * SEQ + t] = x[(b0 + r) * SEQ + t];
    }
    for (int i = tid; i < 8 * HID; i += 128) h_sh[i] = 0.f;

    const float bh0 = bh[j0], bh1 = bh[j1];
    __syncthreads();

    // Prefetch step-0 inputs
    float xv0[4], xv1[4];
#pragma unroll
    for (int r = 0; r < 4; r++) {
        const int tok = tok_sh[(rg * 4 + r) * SEQ + 0];
        xv0[r] = g_P[(long)tok * HID + j0] + bh0;
        xv1[r] = g_P[(long)tok * HID + j1] + bh1;
    }

    for (int t = 0; t < SEQ; t++) {
        float acc0[4], acc1[4];
#pragma unroll
        for (int r = 0; r < 4; r++) { acc0[r] = xv0[r]; acc1[r] = xv1[r]; }

        // Prefetch next timestep (latency hidden under the k-loop)
        if (t + 1 < SEQ) {
#pragma unroll
            for (int r = 0; r < 4; r++) {
                const int tok = tok_sh[(rg * 4 + r) * SEQ + t + 1];
                xv0[r] = g_P[(long)tok * HID + j0] + bh0;
                xv1[r] = g_P[(long)tok * HID + j1] + bh1;
            }
        }

        const float* hrow = h_sh + (rg * 4) * HID;
#pragma unroll 8
        for (int k = 0; k < HID; k++) {
            const float w0 = Whh_sh[k * HID + j0];
            const float w1 = Whh_sh[k * HID + j1];
#pragma unroll
            for (int r = 0; r < 4; r++) {
                const float hv = hrow[r * HID + k];
                acc0[r] += hv * w0;
                acc1[r] += hv * w1;
            }
        }
        __syncthreads();  // all reads of h_sh for step t done
#pragma unroll
        for (int r = 0; r < 4; r++) {
            h_sh[(rg * 4 + r) * HID + j0] = tanhf(acc0[r]);
            h_sh[(rg * 4 + r) * HID + j1] = tanhf(acc1[r]);
        }
        __syncthreads();  // step t+1 may read h_sh
    }

    // Dense(1) + sigmoid: one thread per row (negligible cost)
    if (tid < 8) {
        float s = 0.f;
        for (int j = 0; j < HID; j++) s += h_sh[tid * HID + j] * Wd[j];
        s += bd[0];
        out[b0 + tid] = 1.f / (1.f + expf(-s));
    }
}

// ---------------------------------------------------------------------------
extern "C" void kernel_launch(void* const* d_in, const int* in_sizes, int n_in,
                              void* d_out, int out_size) {
    const int*   x   = (const int*)d_in[0];
    const float* emb = (const float*)d_in[1];
    const float* Wxh = (const float*)d_in[2];
    const float* Whh = (const float*)d_in[3];
    const float* bh  = (const float*)d_in[4];
    const float* Wd  = (const float*)d_in[5];
    const float* bd  = (const float*)d_in[6];
    float* out = (float*)d_out;

    proj_kernel<<<(VOCAB + TM - 1) / TM, 256>>>(emb, Wxh);

    const int smem = (HID * HID + 8 * HID) * sizeof(float) + 8 * SEQ * sizeof(int);
    cudaFuncSetAttribute(rnn_kernel, cudaFuncAttributeMaxDynamicSharedMemorySize, smem);
    rnn_kernel<<<BATCH / 8, 128, smem>>>(x, Whh, bh, Wd, bd, out);
}

// round 2
// speedup vs baseline: 1.4175x; 1.4175x over previous
#include <cuda_runtime.h>
#include <math.h>

#define VOCAB 50000
#define EMB   300
#define SEQ   80
#define HID   128
#define BATCH 4096

// Scratch: projected embedding table P = emb @ Wxh  (25.6 MB, L2-resident at use time)
__device__ float g_P[VOCAB * HID];

// ---------------------------------------------------------------------------
// Kernel A: P[v][j] = sum_e emb[v][e] * Wxh[e][j]
// 128x128 tile, TK=4, 256 threads, 8x8 per-thread tile, register-prefetch
// software pipeline to hide global-load latency.
// ---------------------------------------------------------------------------
__global__ __launch_bounds__(256) void proj_kernel(const float* __restrict__ emb,
                                                   const float* __restrict__ Wxh) {
    __shared__ float As[4][128];   // [k][row]
    __shared__ float Bs[4][128];   // [k][col]

    const int tid = threadIdx.x;
    const int v0  = blockIdx.x * 128;
    const int tr  = tid >> 4;   // 0..15 -> rows tr*8..+7
    const int tc  = tid & 15;   // 0..15 -> cols tc*8..+7

    float acc[8][8];
#pragma unroll
    for (int i = 0; i < 8; i++)
#pragma unroll
        for (int j = 0; j < 8; j++) acc[i][j] = 0.f;

    // Loader roles: tid<128 loads A (one emb row, 4 floats), tid>=128 loads B.
    const bool  isA = (tid < 128);
    const int   av  = v0 + tid;                  // A: vocab row
    const int   bk  = (tid - 128) >> 5;          // B: k row 0..3
    const int   bj  = ((tid - 128) & 31) * 4;    // B: col group

    float4 ld;   // prefetch register
    {
        if (isA) {
            ld = (av < VOCAB) ? *(const float4*)&emb[(long)av * EMB + 0]
                              : make_float4(0.f, 0.f, 0.f, 0.f);
        } else {
            ld = *(const float4*)&Wxh[(0 + bk) * HID + bj];
        }
    }

    for (int e0 = 0; e0 < EMB; e0 += 4) {
        // Commit prefetched tile to smem
        if (isA) {
            As[0][tid] = ld.x; As[1][tid] = ld.y; As[2][tid] = ld.z; As[3][tid] = ld.w;
        } else {
            *(float4*)&Bs[bk][bj] = ld;
        }
        __syncthreads();

        // Issue next tile's loads (latency hidden under compute)
        const int en = e0 + 4;
        if (en < EMB) {
            if (isA) {
                ld = (av < VOCAB) ? *(const float4*)&emb[(long)av * EMB + en]
                                  : make_float4(0.f, 0.f, 0.f, 0.f);
            } else {
                ld = *(const float4*)&Wxh[(en + bk) * HID + bj];
            }
        }

#pragma unroll
        for (int k = 0; k < 4; k++) {
            float a[8], b[8];
            *(float4*)&a[0] = *(float4*)&As[k][tr * 8];
            *(float4*)&a[4] = *(float4*)&As[k][tr * 8 + 4];
            *(float4*)&b[0] = *(float4*)&Bs[k][tc * 8];
            *(float4*)&b[4] = *(float4*)&Bs[k][tc * 8 + 4];
#pragma unroll
            for (int i = 0; i < 8; i++)
#pragma unroll
                for (int j = 0; j < 8; j++) acc[i][j] += a[i] * b[j];
        }
        __syncthreads();
    }

#pragma unroll
    for (int i = 0; i < 8; i++) {
        const int v = v0 + tr * 8 + i;
        if (v < VOCAB) {
            *(float4*)&g_P[(long)v * HID + tc * 8]     = *(float4*)&acc[i][0];
            *(float4*)&g_P[(long)v * HID + tc * 8 + 4] = *(float4*)&acc[i][4];
        }
    }
}

// ---------------------------------------------------------------------------
// Kernel B: persistent-style recurrence. grid=148 (one block/SM), 224 threads
// (7 warps). Each warp = one rowgroup of 4 batch rows; block owns 27-28 rows.
// Thread tile: 4 rows x 4 cols. k-loop unrolled by 4 with all-vector LDS:
// per 4k: 4 LDS.128 (h) + 4 LDS.128 (Whh) + 64 FFMA  ->  89% FMA fraction.
// Double-buffered h: ONE barrier per timestep.
// ---------------------------------------------------------------------------
#define NBLK   148
#define NTHR   224
#define NSLOT  28     // 7 warps * 4 rows

__global__ __launch_bounds__(NTHR) void rnn_kernel(const int* __restrict__ x,
                                                   const float* __restrict__ Whh,
                                                   const float* __restrict__ bh,
                                                   const float* __restrict__ Wd,
                                                   const float* __restrict__ bd,
                                                   float* __restrict__ out) {
    extern __shared__ float sh[];
    float* Whh_sh = sh;                              // HID*HID   (64 KB)
    float* hbuf   = Whh_sh + HID * HID;              // 2 * NSLOT*HID (28 KB)
    int*   tok_sh = (int*)(hbuf + 2 * NSLOT * HID);  // NSLOT*SEQ  (8.75 KB)

    const int tid = threadIdx.x;
    const int rg  = tid >> 5;        // warp id = rowgroup 0..6
    const int jt  = tid & 31;
    const int j0  = jt * 4;
    const int bid = blockIdx.x;

    // Row assignment: first 100 blocks get 28 rows, rest get 27.
    int nrows, b0;
    if (bid < BATCH - NBLK * 27) { nrows = 28; b0 = bid * 28; }
    else                         { nrows = 27; b0 = 2800 + (bid - 100) * 27; }

    // Load Whh into smem (vectorized)
    {
        const float4* src = (const float4*)Whh;
        float4* dst = (float4*)Whh_sh;
        for (int i = tid; i < HID * HID / 4; i += NTHR) dst[i] = src[i];
    }
    // Load tokens (clamped row index for padded slots)
    for (int i = tid; i < NSLOT * SEQ; i += NTHR) {
        const int s = i / SEQ, t = i % SEQ;
        int row = b0 + s; if (row > BATCH - 1) row = BATCH - 1;
        tok_sh[s * SEQ + t] = x[row * SEQ + t];
    }
    // Zero h buffer 0
    for (int i = tid; i < NSLOT * HID; i += NTHR) hbuf[i] = 0.f;

    const float4 bhv = *(const float4*)&bh[j0];
    __syncthreads();

    // Prefetch step-0 inputs
    float4 xv[4];
#pragma unroll
    for (int r = 0; r < 4; r++) {
        const int s = rg * 4 + r;
        const int tok = tok_sh[s * SEQ + 0];
        float4 p = *(const float4*)&g_P[(long)tok * HID + j0];
        xv[r] = make_float4(p.x + bhv.x, p.y + bhv.y, p.z + bhv.z, p.w + bhv.w);
    }

    for (int t = 0; t < SEQ; t++) {
        float* hcur = hbuf + (t & 1) * NSLOT * HID;
        float* hnxt = hbuf + ((t & 1) ^ 1) * NSLOT * HID;

        float acc[4][4];
#pragma unroll
        for (int r = 0; r < 4; r++) {
            acc[r][0] = xv[r].x; acc[r][1] = xv[r].y;
            acc[r][2] = xv[r].z; acc[r][3] = xv[r].w;
        }

        // Prefetch next timestep's P rows (hidden under k-loop)
        if (t + 1 < SEQ) {
#pragma unroll
            for (int r = 0; r < 4; r++) {
                const int s = rg * 4 + r;
                const int tok = tok_sh[s * SEQ + t + 1];
                float4 p = *(const float4*)&g_P[(long)tok * HID + j0];
                xv[r] = make_float4(p.x + bhv.x, p.y + bhv.y, p.z + bhv.z, p.w + bhv.w);
            }
        }

        const float* hrow = hcur + (rg * 4) * HID;
#pragma unroll 4
        for (int k = 0; k < HID; k += 4) {
            float hv[4][4];
#pragma unroll
            for (int r = 0; r < 4; r++)
                *(float4*)&hv[r][0] = *(const float4*)&hrow[r * HID + k];
#pragma unroll
            for (int kk = 0; kk < 4; kk++) {
                float w[4];
                *(float4*)&w[0] = *(const float4*)&Whh_sh[(k + kk) * HID + j0];
#pragma unroll
                for (int r = 0; r < 4; r++) {
#pragma unroll
                    for (int j = 0; j < 4; j++)
                        acc[r][j] += hv[r][kk] * w[j];
                }
            }
        }

        // Activation + store next h (different buffer than reads: no pre-barrier)
#pragma unroll
        for (int r = 0; r < 4; r++) {
            float4 hn;
            hn.x = tanhf(acc[r][0]); hn.y = tanhf(acc[r][1]);
            hn.z = tanhf(acc[r][2]); hn.w = tanhf(acc[r][3]);
            *(float4*)&hnxt[(rg * 4 + r) * HID + j0] = hn;
        }
        __syncthreads();
    }

    // Dense(1) + sigmoid. Final h lives in hbuf[SEQ & 1] == hbuf[0] for SEQ=80.
    const float* hlast = hbuf + (SEQ & 1) * NSLOT * HID;
    const float4 wd4 = *(const float4*)&Wd[j0];
    const float  bd0 = bd[0];
    float part[4];
#pragma unroll
    for (int r = 0; r < 4; r++) {
        const float* hr = hlast + (rg * 4 + r) * HID + j0;
        part[r] = hr[0] * wd4.x + hr[1] * wd4.y + hr[2] * wd4.z + hr[3] * wd4.w;
    }
#pragma unroll
    for (int off = 16; off > 0; off >>= 1) {
#pragma unroll
        for (int r = 0; r < 4; r++)
            part[r] += __shfl_down_sync(0xffffffff, part[r], off);
    }
    if (jt == 0) {
#pragma unroll
        for (int r = 0; r < 4; r++) {
            const int s = rg * 4 + r;
            if (s < nrows)
                out[b0 + s] = 1.f / (1.f + expf(-(part[r] + bd0)));
        }
    }
}

// ---------------------------------------------------------------------------
extern "C" void kernel_launch(void* const* d_in, const int* in_sizes, int n_in,
                              void* d_out, int out_size) {
    const int*   x   = (const int*)d_in[0];
    const float* emb = (const float*)d_in[1];
    const float* Wxh = (const float*)d_in[2];
    const float* Whh = (const float*)d_in[3];
    const float* bh  = (const float*)d_in[4];
    const float* Wd  = (const float*)d_in[5];
    const float* bd  = (const float*)d_in[6];
    float* out = (float*)d_out;

    proj_kernel<<<(VOCAB + 127) / 128, 256>>>(emb, Wxh);

    const int smem = (HID * HID + 2 * NSLOT * HID) * sizeof(float)
                   + NSLOT * SEQ * sizeof(int);
    static int configured = 0;
    cudaFuncSetAttribute(rnn_kernel, cudaFuncAttributeMaxDynamicSharedMemorySize, smem);
    (void)configured;
    rnn_kernel<<<NBLK, NTHR, smem>>>(x, Whh, bh, Wd, bd, out);
}